// round 9
// baseline (speedup 1.0000x reference)
#include <cuda_runtime.h>
#include <cuda_bf16.h>
#include <cstdint>

#define D_  1024
#define H_  16
#define HD_ 64
#define B_  2
#define S_  2048
#define M_  (B_*S_)   // 4096

typedef __nv_bfloat16 bf;

// ---------------- scratch planes (bf16 hi/lo) ----------------
__device__ bf g_xh[M_*D_], g_xl[M_*D_];       // split X [B*S, D]
__device__ bf g_wh[4*D_*D_], g_wl[4*D_*D_];   // transposed W [N,K] x4
__device__ bf g_qh[M_*D_], g_ql[M_*D_];       // [B,H,S,HD]
__device__ bf g_kh[M_*D_], g_kl[M_*D_];
__device__ bf g_vh[M_*D_], g_vl[M_*D_];
__device__ bf g_ah[M_*D_], g_al[M_*D_];       // attn out [B,S,D]

// ================= helpers =================
__device__ __forceinline__ uint32_t smem_u32(const void* p){
    uint32_t a;
    asm("{ .reg .u64 t; cvta.to.shared.u64 t, %1; cvt.u32.u64 %0, t; }":"=r"(a):"l"(p));
    return a;
}
__device__ __forceinline__ float ex2f(float x){
    float y; asm("ex2.approx.ftz.f32 %0, %1;":"=f"(y):"f"(x)); return y;
}
__device__ __forceinline__ uint32_t bfpack(float x, float y){
    __nv_bfloat162 t = __floats2bfloat162_rn(x, y);
    return *reinterpret_cast<uint32_t*>(&t);
}
__device__ __forceinline__ void split2(float x, float y, uint32_t& hi, uint32_t& lo){
    __nv_bfloat16 hx = __float2bfloat16_rn(x), hy = __float2bfloat16_rn(y);
    __nv_bfloat162 hh; hh.x = hx; hh.y = hy;
    hi = *reinterpret_cast<uint32_t*>(&hh);
    lo = bfpack(x - __bfloat162float(hx), y - __bfloat162float(hy));
}

#define LDSM4(R,A)  asm volatile("ldmatrix.sync.aligned.m8n8.x4.shared.b16 {%0,%1,%2,%3}, [%4];" \
    :"=r"((R)[0]),"=r"((R)[1]),"=r"((R)[2]),"=r"((R)[3]):"r"(A))
#define LDSM4T(R,A) asm volatile("ldmatrix.sync.aligned.m8n8.x4.trans.shared.b16 {%0,%1,%2,%3}, [%4];" \
    :"=r"((R)[0]),"=r"((R)[1]),"=r"((R)[2]),"=r"((R)[3]):"r"(A))
#define MMA16816(C,A,Bv) asm volatile( \
    "mma.sync.aligned.m16n8k16.row.col.f32.bf16.bf16.f32 {%0,%1,%2,%3},{%4,%5,%6,%7},{%8,%9},{%0,%1,%2,%3};" \
    :"+f"((C)[0]),"+f"((C)[1]),"+f"((C)[2]),"+f"((C)[3]) \
    :"r"((A)[0]),"r"((A)[1]),"r"((A)[2]),"r"((A)[3]),"r"((Bv)[0]),"r"((Bv)[1]))

#define CP16(dst,src) asm volatile("cp.async.cg.shared.global [%0], [%1], 16;"::"r"(dst),"l"(src):"memory")
#define CP_COMMIT()   asm volatile("cp.async.commit_group;":::"memory")
#define CP_WAIT1()    asm volatile("cp.async.wait_group 1;":::"memory")
#define CP_WAIT0()    asm volatile("cp.async.wait_group 0;":::"memory")

// conflict-free XOR swizzle for 128B rows (byte offset)
__device__ __forceinline__ uint32_t swz128(int row, int c){ return (uint32_t)(row*128 + ((c ^ (row&7))<<4)); }

// ================= prep: split X into bf16 hi/lo planes =================
__global__ void __launch_bounds__(256)
split_x(const float* __restrict__ X)
{
    const int i0 = (blockIdx.x*256 + threadIdx.x)*8;
    float4 a = *reinterpret_cast<const float4*>(X + i0);
    float4 b = *reinterpret_cast<const float4*>(X + i0 + 4);
    uint4 h, lo;
    split2(a.x,a.y,h.x,lo.x); split2(a.z,a.w,h.y,lo.y);
    split2(b.x,b.y,h.z,lo.z); split2(b.z,b.w,h.w,lo.w);
    *reinterpret_cast<uint4*>(&g_xh[i0]) = h;
    *reinterpret_cast<uint4*>(&g_xl[i0]) = lo;
}

// ================= prep: transpose W -> bf16 hi/lo [N,K] =================
__global__ void __launch_bounds__(256)
transpose_w(const float* __restrict__ Wq, const float* __restrict__ Wk,
            const float* __restrict__ Wv, const float* __restrict__ Wo)
{
    __shared__ float t[32][33];
    const int z = blockIdx.z;
    const float* W = (z==0)?Wq:(z==1)?Wk:(z==2)?Wv:Wo;
    bf* Oh = g_wh + (size_t)z*D_*D_;
    bf* Ol = g_wl + (size_t)z*D_*D_;
    const int bx = blockIdx.x*32, by = blockIdx.y*32;
    const int tx = threadIdx.x&31, ty = threadIdx.x>>5;
    #pragma unroll
    for (int r=0;r<32;r+=8) t[ty+r][tx] = W[(size_t)(by+ty+r)*D_ + bx+tx];
    __syncthreads();
    #pragma unroll
    for (int r=0;r<32;r+=8){
        const float v = t[tx][ty+r];
        const bf h = __float2bfloat16_rn(v);
        const size_t o = (size_t)(bx+ty+r)*D_ + by+tx;
        Oh[o] = h;
        Ol[o] = __float2bfloat16_rn(v - __bfloat162float(h));
    }
}

// ================= bf16x3 GEMM: 128x128 tile, k-chunk 64, 3-stage =================
// stage: Ah(16K) Al(16K) Bh(16K) Bl(16K) = 64KB, 128B rows swz128
#define GPL  16384
#define GSTG (4*GPL)
#define GSMEM (3*GSTG)   // 196608

template<int MODE>  // 0: head-layout bf16 hi/lo out; 1: flat fp32 out
__device__ __forceinline__ void gemm_body(const bf* __restrict__ Ah, const bf* __restrict__ Al,
                                          const bf* __restrict__ Bh, const bf* __restrict__ Bl,
                                          const float* __restrict__ bias,
                                          float* __restrict__ outf,
                                          bf* __restrict__ oh, bf* __restrict__ ol)
{
    extern __shared__ __align__(128) char sm[];
    const uint32_t su = smem_u32(sm);
    const int tid = threadIdx.x, l = tid&31, w = tid>>5;
    const int wm = (w&3)*32, wn = (w>>2)*64;
    const int m0 = blockIdx.y*128, n0 = blockIdx.x*128;

    const int p = tid>>6, sub = tid&63;
    const bf* srcb = (p==0)?Ah:(p==1)?Al:(p==2)?Bh:Bl;
    const int rbase = (p<2)?m0:n0;

    #define G_ISSUE(ch) do{ \
        const uint32_t _st = su + (uint32_t)((ch)%3)*GSTG + p*GPL; \
        const bf* _sp = srcb + (size_t)rbase*D_ + (ch)*64; \
        _Pragma("unroll") for (int i=0;i<16;i++){ \
            const int _idx = sub + 64*i, _r = _idx>>3, _c = _idx&7; \
            CP16(_st + swz128(_r,_c), _sp + (size_t)_r*D_ + _c*8); } \
        CP_COMMIT(); }while(0)

    float C[2][8][4];
    #pragma unroll
    for (int mt=0;mt<2;mt++)
        #pragma unroll
        for (int nt=0;nt<8;nt++){ C[mt][nt][0]=0.f;C[mt][nt][1]=0.f;C[mt][nt][2]=0.f;C[mt][nt][3]=0.f; }

    G_ISSUE(0); G_ISSUE(1);

    const int g = l>>3;
    const int arow0 = wm + (l&15);
    const int brow0 = wn + ((g>>1)&1)*8 + (l&7);

    const int NCH = 16;
    for (int c=0;c<NCH;c++){
        if (c<NCH-2) CP_WAIT1(); else CP_WAIT0();
        __syncthreads();
        if (c+2<NCH) G_ISSUE(c+2);
        const uint32_t sb = su + (uint32_t)(c%3)*GSTG;
        #pragma unroll
        for (int ks=0;ks<4;ks++){
            uint32_t ah[2][4], al2[2][4];
            #pragma unroll
            for (int mt=0;mt<2;mt++){
                const uint32_t a = sb + swz128(arow0 + mt*16, ks*2 + (l>>4));
                LDSM4(ah[mt], a);
                LDSM4(al2[mt], a + GPL);
            }
            uint32_t bh4[4][4], bl4[4][4];
            #pragma unroll
            for (int pr=0;pr<4;pr++){
                const uint32_t b = sb + 2*GPL + swz128(brow0 + pr*16, ks*2 + (g&1));
                LDSM4(bh4[pr], b);
                LDSM4(bl4[pr], b + GPL);
            }
            // term-major: long C-reuse distance
            #pragma unroll
            for (int mt=0;mt<2;mt++)
                #pragma unroll
                for (int pr=0;pr<4;pr++){
                    MMA16816(C[mt][pr*2+0], ah[mt], &bh4[pr][0]);
                    MMA16816(C[mt][pr*2+1], ah[mt], &bh4[pr][2]);
                }
            #pragma unroll
            for (int mt=0;mt<2;mt++)
                #pragma unroll
                for (int pr=0;pr<4;pr++){
                    MMA16816(C[mt][pr*2+0], ah[mt], &bl4[pr][0]);
                    MMA16816(C[mt][pr*2+1], ah[mt], &bl4[pr][2]);
                }
            #pragma unroll
            for (int mt=0;mt<2;mt++)
                #pragma unroll
                for (int pr=0;pr<4;pr++){
                    MMA16816(C[mt][pr*2+0], al2[mt], &bh4[pr][0]);
                    MMA16816(C[mt][pr*2+1], al2[mt], &bh4[pr][2]);
                }
        }
    }

    #pragma unroll
    for (int mt=0;mt<2;mt++){
        #pragma unroll
        for (int nt=0;nt<8;nt++){
            const int col = n0 + wn + nt*8 + (l&3)*2;
            const float bx = bias[col], by = bias[col+1];
            #pragma unroll
            for (int hh=0;hh<2;hh++){
                const int row = m0 + wm + mt*16 + (l>>2) + hh*8;
                const float vx = C[mt][nt][hh*2+0] + bx;
                const float vy = C[mt][nt][hh*2+1] + by;
                if (MODE==0){
                    uint32_t h, lo; split2(vx, vy, h, lo);
                    const int b = row>>11, sq = row&(S_-1);
                    const int hd_h = col>>6, hd = col&(HD_-1);
                    const size_t o = (((size_t)b*H_+hd_h)*S_+sq)*HD_+hd;
                    *reinterpret_cast<uint32_t*>(&oh[o]) = h;
                    *reinterpret_cast<uint32_t*>(&ol[o]) = lo;
                } else {
                    float2 v; v.x = vx; v.y = vy;
                    *reinterpret_cast<float2*>(&outf[(size_t)row*D_ + col]) = v;
                }
            }
        }
    }
    #undef G_ISSUE
}

__global__ void __launch_bounds__(256)
qkv_k(const float* __restrict__ bq, const float* __restrict__ bk, const float* __restrict__ bv)
{
    const int z = blockIdx.z;
    const float* bias = (z==0)?bq:(z==1)?bk:bv;
    bf* oh = (z==0)?g_qh:(z==1)?g_kh:g_vh;
    bf* ol = (z==0)?g_ql:(z==1)?g_kl:g_vl;
    gemm_body<0>(g_xh, g_xl, g_wh + (size_t)z*D_*D_, g_wl + (size_t)z*D_*D_,
                 bias, nullptr, oh, ol);
}

__global__ void __launch_bounds__(256)
out_k(const float* __restrict__ bo, float* __restrict__ out)
{
    gemm_body<1>(g_ah, g_al, g_wh + (size_t)3*D_*D_, g_wl + (size_t)3*D_*D_,
                 bo, out, nullptr, nullptr);
}

// ================= flash attention (static-offset softmax, 3-stage KV) =================
// smem: Qh@0 (16K), Ql@16K, KV stages @32K: Kh(8K) Kl(8K) Vh(8K) Vl(8K) x3
#define APL  8192
#define AQ   16384
#define AKV0 32768
#define ASTG 32768
#define ASMEM (AKV0 + 3*ASTG)   // 131072

__global__ void __launch_bounds__(256)
attn_k()
{
    extern __shared__ __align__(128) char sm[];
    const uint32_t su = smem_u32(sm);
    const int tid = threadIdx.x, l = tid&31, w = tid>>5;
    const int bhid = blockIdx.y, qt = blockIdx.x;
    const int wm = w*16;
    const size_t bh_off = (size_t)bhid*S_*HD_;

    // Q cp.async: 2 planes x 128 rows x 8 chunks
    {
        const int p2 = tid>>7, sub2 = tid&127;
        const bf* qs = ((p2==0)?g_qh:g_ql) + bh_off + (size_t)qt*128*HD_;
        const uint32_t qdst = su + p2*AQ;
        #pragma unroll
        for (int i=0;i<8;i++){
            const int idx = sub2 + 128*i, r = idx>>3, c = idx&7;
            CP16(qdst + swz128(r,c), qs + (size_t)r*HD_ + c*8);
        }
    }

    const int p = tid>>6, sub = tid&63;
    const bf* kvsrc = ((p==0)?g_kh:(p==1)?g_kl:(p==2)?g_vh:g_vl) + bh_off;
    #define A_ISSUE(it) do{ \
        const uint32_t _st = su + AKV0 + (uint32_t)((it)%3)*ASTG + p*APL; \
        const bf* _sp = kvsrc + (size_t)(it)*64*HD_; \
        _Pragma("unroll") for (int i=0;i<8;i++){ \
            const int _idx = sub + 64*i, _r = _idx>>3, _c = _idx&7; \
            CP16(_st + swz128(_r,_c), _sp + (size_t)_r*HD_ + _c*8); } \
        CP_COMMIT(); }while(0)

    A_ISSUE(0);   // group 0 includes Q copies
    A_ISSUE(1);

    float O[8][4];
    #pragma unroll
    for (int nt=0;nt<8;nt++){ O[nt][0]=0.f;O[nt][1]=0.f;O[nt][2]=0.f;O[nt][3]=0.f; }
    float lrun[2] = {0.f,0.f};
    const float SC = 0.18033688011f;   // 0.125 * log2(e); constant offset cancels in 1/l

    uint32_t qh[4][4], ql[4][4];
    const int g = l>>3;
    const int qrow = wm + (l&15);
    const int krow0 = ((g>>1)&1)*8 + (l&7);
    const int vrow0 = (l&15);

    const int NIT = S_/64;
    for (int it=0; it<NIT; ++it){
        if (it<NIT-2) CP_WAIT1(); else CP_WAIT0();
        __syncthreads();
        if (it==0){
            #pragma unroll
            for (int ks=0;ks<4;ks++){
                const uint32_t a = su + swz128(qrow, ks*2 + (l>>4));
                LDSM4(qh[ks], a);
                LDSM4(ql[ks], a + AQ);
            }
        }
        if (it+2 < NIT) A_ISSUE(it+2);
        const uint32_t sb = su + AKV0 + (uint32_t)(it%3)*ASTG;

        // ---- S = Q @ K^T (term-major) ----
        float Sv[8][4];
        #pragma unroll
        for (int nt=0;nt<8;nt++){ Sv[nt][0]=0.f;Sv[nt][1]=0.f;Sv[nt][2]=0.f;Sv[nt][3]=0.f; }
        #pragma unroll
        for (int ks=0;ks<4;ks++){
            uint32_t kh4[4][4], kl4[4][4];
            #pragma unroll
            for (int pr=0;pr<4;pr++){
                const uint32_t ka = sb + swz128(krow0 + pr*16, ks*2 + (g&1));
                LDSM4(kh4[pr], ka);
                LDSM4(kl4[pr], ka + APL);
            }
            #pragma unroll
            for (int pr=0;pr<4;pr++){
                MMA16816(Sv[pr*2+0], qh[ks], &kh4[pr][0]);
                MMA16816(Sv[pr*2+1], qh[ks], &kh4[pr][2]);
            }
            #pragma unroll
            for (int pr=0;pr<4;pr++){
                MMA16816(Sv[pr*2+0], qh[ks], &kl4[pr][0]);
                MMA16816(Sv[pr*2+1], qh[ks], &kl4[pr][2]);
            }
            #pragma unroll
            for (int pr=0;pr<4;pr++){
                MMA16816(Sv[pr*2+0], ql[ks], &kh4[pr][0]);
                MMA16816(Sv[pr*2+1], ql[ks], &kh4[pr][2]);
            }
        }

        // ---- softmax numerator (no running max; offset cancels in 1/l) ----
        #pragma unroll
        for (int hh=0;hh<2;hh++){
            const int i0 = hh*2;
            float sum = 0.f;
            #pragma unroll
            for (int nt=0;nt<8;nt++){
                Sv[nt][i0]   = ex2f(Sv[nt][i0]  *SC); sum += Sv[nt][i0];
                Sv[nt][i0+1] = ex2f(Sv[nt][i0+1]*SC); sum += Sv[nt][i0+1];
            }
            sum += __shfl_xor_sync(0xffffffffu, sum, 1);
            sum += __shfl_xor_sync(0xffffffffu, sum, 2);
            lrun[hh] += sum;
        }

        // ---- O += P @ V (term-major) ----
        #pragma unroll
        for (int kt=0;kt<4;kt++){
            uint32_t ph[4], pl[4];
            split2(Sv[2*kt][0],   Sv[2*kt][1],   ph[0], pl[0]);
            split2(Sv[2*kt][2],   Sv[2*kt][3],   ph[1], pl[1]);
            split2(Sv[2*kt+1][0], Sv[2*kt+1][1], ph[2], pl[2]);
            split2(Sv[2*kt+1][2], Sv[2*kt+1][3], ph[3], pl[3]);
            uint32_t vh4[4][4], vl4[4][4];
            #pragma unroll
            for (int pr=0;pr<4;pr++){
                const uint32_t va = sb + 2*APL + swz128(kt*16 + vrow0, pr*2 + (l>>4));
                LDSM4T(vh4[pr], va);
                LDSM4T(vl4[pr], va + APL);
            }
            #pragma unroll
            for (int pr=0;pr<4;pr++){
                MMA16816(O[pr*2+0], ph, &vh4[pr][0]);
                MMA16816(O[pr*2+1], ph, &vh4[pr][2]);
            }
            #pragma unroll
            for (int pr=0;pr<4;pr++){
                MMA16816(O[pr*2+0], ph, &vl4[pr][0]);
                MMA16816(O[pr*2+1], ph, &vl4[pr][2]);
            }
            #pragma unroll
            for (int pr=0;pr<4;pr++){
                MMA16816(O[pr*2+0], pl, &vh4[pr][0]);
                MMA16816(O[pr*2+1], pl, &vh4[pr][2]);
            }
        }
    }

    // ---- normalize + write hi/lo planes [B,S,D] ----
    const int b = bhid>>4, hhead = bhid&15;
    #pragma unroll
    for (int hh=0;hh<2;hh++){
        const float inv = 1.f / lrun[hh];
        const int row = qt*128 + wm + (l>>2) + hh*8;
        const size_t obase = ((size_t)b*S_ + row)*D_ + hhead*HD_;
        #pragma unroll
        for (int nt=0;nt<8;nt++){
            uint32_t h, lo;
            split2(O[nt][hh*2+0]*inv, O[nt][hh*2+1]*inv, h, lo);
            const size_t o = obase + nt*8 + (l&3)*2;
            *reinterpret_cast<uint32_t*>(&g_ah[o]) = h;
            *reinterpret_cast<uint32_t*>(&g_al[o]) = lo;
        }
    }
    #undef A_ISSUE
}

// ---------------- launch ----------------
extern "C" void kernel_launch(void* const* d_in, const int* in_sizes, int n_in,
                              void* d_out, int out_size)
{
    const float* X  = (const float*)d_in[0];
    const float* Wq = (const float*)d_in[1];
    const float* bq = (const float*)d_in[2];
    const float* Wk = (const float*)d_in[3];
    const float* bk = (const float*)d_in[4];
    const float* Wv = (const float*)d_in[5];
    const float* bv = (const float*)d_in[6];
    const float* Wo = (const float*)d_in[7];
    const float* bo = (const float*)d_in[8];
    float* out = (float*)d_out;

    cudaFuncSetAttribute(qkv_k,  cudaFuncAttributeMaxDynamicSharedMemorySize, GSMEM);
    cudaFuncSetAttribute(out_k,  cudaFuncAttributeMaxDynamicSharedMemorySize, GSMEM);
    cudaFuncSetAttribute(attn_k, cudaFuncAttributeMaxDynamicSharedMemorySize, ASMEM);

    split_x<<<M_*D_/(256*8), 256>>>(X);
    transpose_w<<<dim3(32,32,4), 256>>>(Wq, Wk, Wv, Wo);
    qkv_k<<<dim3(D_/128, M_/128, 3), 256, GSMEM>>>(bq, bk, bv);
    attn_k<<<dim3(S_/128, B_*H_), 256, ASMEM>>>();
    out_k<<<dim3(D_/128, M_/128), 256, GSMEM>>>(bo, out);
}

// round 10
// speedup vs baseline: 1.0723x; 1.0723x over previous
#include <cuda_runtime.h>
#include <cuda_bf16.h>
#include <cstdint>

#define D_  1024
#define H_  16
#define HD_ 64
#define B_  2
#define S_  2048
#define M_  (B_*S_)   // 4096

typedef __nv_bfloat16 bf;

// ---------------- scratch planes (bf16 hi/lo) ----------------
__device__ bf g_xh[M_*D_], g_xl[M_*D_];       // split X [B*S, D]
__device__ bf g_wh[4*D_*D_], g_wl[4*D_*D_];   // transposed W [N,K] x4
__device__ bf g_qh[M_*D_], g_ql[M_*D_];       // [B,H,S,HD]
__device__ bf g_kh[M_*D_], g_kl[M_*D_];
__device__ bf g_vh[M_*D_], g_vl[M_*D_];
__device__ bf g_ah[M_*D_], g_al[M_*D_];       // attn out [B,S,D]

// ================= helpers =================
__device__ __forceinline__ uint32_t smem_u32(const void* p){
    uint32_t a;
    asm("{ .reg .u64 t; cvta.to.shared.u64 t, %1; cvt.u32.u64 %0, t; }":"=r"(a):"l"(p));
    return a;
}
__device__ __forceinline__ float ex2f(float x){
    float y; asm("ex2.approx.ftz.f32 %0, %1;":"=f"(y):"f"(x)); return y;
}
__device__ __forceinline__ uint32_t bfpack(float x, float y){
    __nv_bfloat162 t = __floats2bfloat162_rn(x, y);
    return *reinterpret_cast<uint32_t*>(&t);
}
__device__ __forceinline__ void split2(float x, float y, uint32_t& hi, uint32_t& lo){
    __nv_bfloat16 hx = __float2bfloat16_rn(x), hy = __float2bfloat16_rn(y);
    __nv_bfloat162 hh; hh.x = hx; hh.y = hy;
    hi = *reinterpret_cast<uint32_t*>(&hh);
    lo = bfpack(x - __bfloat162float(hx), y - __bfloat162float(hy));
}

#define LDSM4(R,A)  asm volatile("ldmatrix.sync.aligned.m8n8.x4.shared.b16 {%0,%1,%2,%3}, [%4];" \
    :"=r"((R)[0]),"=r"((R)[1]),"=r"((R)[2]),"=r"((R)[3]):"r"(A))
#define LDSM4T(R,A) asm volatile("ldmatrix.sync.aligned.m8n8.x4.trans.shared.b16 {%0,%1,%2,%3}, [%4];" \
    :"=r"((R)[0]),"=r"((R)[1]),"=r"((R)[2]),"=r"((R)[3]):"r"(A))
#define MMA16816(C,A,Bv) asm volatile( \
    "mma.sync.aligned.m16n8k16.row.col.f32.bf16.bf16.f32 {%0,%1,%2,%3},{%4,%5,%6,%7},{%8,%9},{%0,%1,%2,%3};" \
    :"+f"((C)[0]),"+f"((C)[1]),"+f"((C)[2]),"+f"((C)[3]) \
    :"r"((A)[0]),"r"((A)[1]),"r"((A)[2]),"r"((A)[3]),"r"((Bv)[0]),"r"((Bv)[1]))

#define CP16(dst,src) asm volatile("cp.async.cg.shared.global [%0], [%1], 16;"::"r"(dst),"l"(src):"memory")
#define CP_COMMIT()   asm volatile("cp.async.commit_group;":::"memory")
#define CP_WAIT1()    asm volatile("cp.async.wait_group 1;":::"memory")
#define CP_WAIT0()    asm volatile("cp.async.wait_group 0;":::"memory")

// conflict-free XOR swizzles (byte offsets)
__device__ __forceinline__ uint32_t swz64 (int row, int c){ return (uint32_t)(row*64  + ((c ^ ((row>>1)&3))<<4)); }
__device__ __forceinline__ uint32_t swz128(int row, int c){ return (uint32_t)(row*128 + ((c ^ (row&7))<<4)); }

// ================= prep: split X into bf16 hi/lo planes =================
__global__ void __launch_bounds__(256)
split_x(const float* __restrict__ X)
{
    const int i0 = (blockIdx.x*256 + threadIdx.x)*8;
    float4 a = *reinterpret_cast<const float4*>(X + i0);
    float4 b = *reinterpret_cast<const float4*>(X + i0 + 4);
    uint4 h, lo;
    split2(a.x,a.y,h.x,lo.x); split2(a.z,a.w,h.y,lo.y);
    split2(b.x,b.y,h.z,lo.z); split2(b.z,b.w,h.w,lo.w);
    *reinterpret_cast<uint4*>(&g_xh[i0]) = h;
    *reinterpret_cast<uint4*>(&g_xl[i0]) = lo;
}

// ================= prep: transpose W -> bf16 hi/lo [N,K] =================
__global__ void __launch_bounds__(256)
transpose_w(const float* __restrict__ Wq, const float* __restrict__ Wk,
            const float* __restrict__ Wv, const float* __restrict__ Wo)
{
    __shared__ float t[32][33];
    const int z = blockIdx.z;
    const float* W = (z==0)?Wq:(z==1)?Wk:(z==2)?Wv:Wo;
    bf* Oh = g_wh + (size_t)z*D_*D_;
    bf* Ol = g_wl + (size_t)z*D_*D_;
    const int bx = blockIdx.x*32, by = blockIdx.y*32;
    const int tx = threadIdx.x&31, ty = threadIdx.x>>5;
    #pragma unroll
    for (int r=0;r<32;r+=8) t[ty+r][tx] = W[(size_t)(by+ty+r)*D_ + bx+tx];
    __syncthreads();
    #pragma unroll
    for (int r=0;r<32;r+=8){
        const float v = t[tx][ty+r];
        const bf h = __float2bfloat16_rn(v);
        const size_t o = (size_t)(bx+ty+r)*D_ + by+tx;
        Oh[o] = h;
        Ol[o] = __float2bfloat16_rn(v - __bfloat162float(h));
    }
}

// ================= bf16x3 GEMM: 128x128 tile, k-chunk 32, 3-stage (R4 config) =================
// stage: Ah(8K) Al(8K) Bh(8K) Bl(8K) = 32KB, 64B rows swz64
#define GPLANE 8192
#define GSTG   32768
#define GSMEM  (3*GSTG)   // 98304

template<int MODE>  // 0: head-layout bf16 hi/lo out; 1: flat fp32 out
__device__ __forceinline__ void gemm_body(const bf* __restrict__ Ah, const bf* __restrict__ Al,
                                          const bf* __restrict__ Bh, const bf* __restrict__ Bl,
                                          const float* __restrict__ bias,
                                          float* __restrict__ outf,
                                          bf* __restrict__ oh, bf* __restrict__ ol)
{
    extern __shared__ __align__(128) char sm[];
    const uint32_t su = smem_u32(sm);
    const int tid = threadIdx.x, l = tid&31, w = tid>>5;
    const int wm = (w&3)*32, wn = (w>>2)*64;
    const int m0 = blockIdx.y*128, n0 = blockIdx.x*128;

    const int p = tid>>6, sub = tid&63;
    const bf* srcb = (p==0)?Ah:(p==1)?Al:(p==2)?Bh:Bl;
    const int rbase = (p<2)?m0:n0;

    #define G_ISSUE(ch) do{ \
        const uint32_t _st = su + (uint32_t)((ch)%3)*GSTG + p*GPLANE; \
        const bf* _sp = srcb + (size_t)rbase*D_ + (ch)*32; \
        _Pragma("unroll") for (int i=0;i<8;i++){ \
            const int _idx = sub + 64*i, _r = _idx>>2, _c = _idx&3; \
            CP16(_st + swz64(_r,_c), _sp + (size_t)_r*D_ + _c*8); } \
        CP_COMMIT(); }while(0)

    float C[2][8][4];
    #pragma unroll
    for (int mt=0;mt<2;mt++)
        #pragma unroll
        for (int nt=0;nt<8;nt++){ C[mt][nt][0]=0.f;C[mt][nt][1]=0.f;C[mt][nt][2]=0.f;C[mt][nt][3]=0.f; }

    G_ISSUE(0); G_ISSUE(1);

    const int g = l>>3;
    const int arow0 = wm + (l&15);
    const int brow0 = wn + ((g>>1)&1)*8 + (l&7);

    for (int c=0;c<32;c++){
        if (c<30) CP_WAIT1(); else CP_WAIT0();
        __syncthreads();
        if (c+2<32) G_ISSUE(c+2);
        const uint32_t sb = su + (uint32_t)(c%3)*GSTG;
        #pragma unroll
        for (int ks=0;ks<2;ks++){
            uint32_t ah[2][4], al2[2][4];
            #pragma unroll
            for (int mt=0;mt<2;mt++){
                const int row = arow0 + mt*16, cc = ks*2 + (l>>4);
                const uint32_t a = sb + swz64(row,cc);
                LDSM4(ah[mt], a);
                LDSM4(al2[mt], a + GPLANE);
            }
            #pragma unroll
            for (int pr=0;pr<4;pr++){
                uint32_t bh4[4], bl4[4];
                const int row = brow0 + pr*16, cc = ks*2 + (g&1);
                const uint32_t b = sb + 2*GPLANE + swz64(row,cc);
                LDSM4(bh4, b);
                LDSM4(bl4, b + GPLANE);
                #pragma unroll
                for (int s2=0;s2<2;s2++){
                    const int nt = pr*2+s2;
                    uint32_t* bh = &bh4[s2*2];
                    uint32_t* bl = &bl4[s2*2];
                    #pragma unroll
                    for (int mt=0;mt<2;mt++){
                        MMA16816(C[mt][nt], ah[mt],  bh);
                        MMA16816(C[mt][nt], ah[mt],  bl);
                        MMA16816(C[mt][nt], al2[mt], bh);
                    }
                }
            }
        }
    }

    #pragma unroll
    for (int mt=0;mt<2;mt++){
        #pragma unroll
        for (int nt=0;nt<8;nt++){
            const int col = n0 + wn + nt*8 + (l&3)*2;
            const float bx = bias[col], by = bias[col+1];
            #pragma unroll
            for (int hh=0;hh<2;hh++){
                const int row = m0 + wm + mt*16 + (l>>2) + hh*8;
                const float vx = C[mt][nt][hh*2+0] + bx;
                const float vy = C[mt][nt][hh*2+1] + by;
                if (MODE==0){
                    uint32_t h, lo; split2(vx, vy, h, lo);
                    const int b = row>>11, sq = row&(S_-1);
                    const int hd_h = col>>6, hd = col&(HD_-1);
                    const size_t o = (((size_t)b*H_+hd_h)*S_+sq)*HD_+hd;
                    *reinterpret_cast<uint32_t*>(&oh[o]) = h;
                    *reinterpret_cast<uint32_t*>(&ol[o]) = lo;
                } else {
                    float2 v; v.x = vx; v.y = vy;
                    *reinterpret_cast<float2*>(&outf[(size_t)row*D_ + col]) = v;
                }
            }
        }
    }
    #undef G_ISSUE
}

__global__ void __launch_bounds__(256,2)
qkv_k(const float* __restrict__ bq, const float* __restrict__ bk, const float* __restrict__ bv)
{
    const int z = blockIdx.z;
    const float* bias = (z==0)?bq:(z==1)?bk:bv;
    bf* oh = (z==0)?g_qh:(z==1)?g_kh:g_vh;
    bf* ol = (z==0)?g_ql:(z==1)?g_kl:g_vl;
    gemm_body<0>(g_xh, g_xl, g_wh + (size_t)z*D_*D_, g_wl + (size_t)z*D_*D_,
                 bias, nullptr, oh, ol);
}

__global__ void __launch_bounds__(256,2)
out_k(const float* __restrict__ bo, float* __restrict__ out)
{
    gemm_body<1>(g_ah, g_al, g_wh + (size_t)3*D_*D_, g_wl + (size_t)3*D_*D_,
                 bo, out, nullptr, nullptr);
}

// ================= flash attention: static softmax, 2-stage KV, 2 CTAs/SM =================
// smem: Qh@0 (16K), Ql@16K, KV stages @32K: Kh(8K) Kl(8K) Vh(8K) Vl(8K) x2 = 96KB total
#define APL  8192
#define AQ   16384
#define AKV0 32768
#define ASTG 32768
#define ASMEM (AKV0 + 2*ASTG)   // 98304

__global__ void __launch_bounds__(256,2)
attn_k()
{
    extern __shared__ __align__(128) char sm[];
    const uint32_t su = smem_u32(sm);
    const int tid = threadIdx.x, l = tid&31, w = tid>>5;
    const int bhid = blockIdx.y, qt = blockIdx.x;
    const int wm = w*16;
    const size_t bh_off = (size_t)bhid*S_*HD_;

    // Q cp.async: 2 planes x 128 rows x 8 chunks (joins group 0)
    {
        const int p2 = tid>>7, sub2 = tid&127;
        const bf* qs = ((p2==0)?g_qh:g_ql) + bh_off + (size_t)qt*128*HD_;
        const uint32_t qdst = su + p2*AQ;
        #pragma unroll
        for (int i=0;i<8;i++){
            const int idx = sub2 + 128*i, r = idx>>3, c = idx&7;
            CP16(qdst + swz128(r,c), qs + (size_t)r*HD_ + c*8);
        }
    }

    const int p = tid>>6, sub = tid&63;
    const bf* kvsrc = ((p==0)?g_kh:(p==1)?g_kl:(p==2)?g_vh:g_vl) + bh_off;
    #define A_ISSUE(it) do{ \
        const uint32_t _st = su + AKV0 + (uint32_t)((it)&1)*ASTG + p*APL; \
        const bf* _sp = kvsrc + (size_t)(it)*64*HD_; \
        _Pragma("unroll") for (int i=0;i<8;i++){ \
            const int _idx = sub + 64*i, _r = _idx>>3, _c = _idx&7; \
            CP16(_st + swz128(_r,_c), _sp + (size_t)_r*HD_ + _c*8); } \
        CP_COMMIT(); }while(0)

    A_ISSUE(0);

    float O[8][4];
    #pragma unroll
    for (int nt=0;nt<8;nt++){ O[nt][0]=0.f;O[nt][1]=0.f;O[nt][2]=0.f;O[nt][3]=0.f; }
    float lrun[2] = {0.f,0.f};
    const float SC = 0.18033688011f;   // 0.125 * log2(e); constant offset cancels in 1/l

    uint32_t qh[4][4], ql[4][4];
    const int g = l>>3;
    const int qrow = wm + (l&15);
    const int krow0 = ((g>>1)&1)*8 + (l&7);
    const int vrow0 = (l&15);

    const int NIT = S_/64;
    for (int it=0; it<NIT; ++it){
        CP_WAIT0();          // stage it%2 full
        __syncthreads();     // also: all warps done reading stage (it+1)%2 from iter it-1
        if (it+1 < NIT) A_ISSUE(it+1);
        if (it==0){
            #pragma unroll
            for (int ks=0;ks<4;ks++){
                const uint32_t a = su + swz128(qrow, ks*2 + (l>>4));
                LDSM4(qh[ks], a);
                LDSM4(ql[ks], a + AQ);
            }
        }
        const uint32_t sb = su + AKV0 + (uint32_t)(it&1)*ASTG;

        // ---- S = Q @ K^T ----
        float Sv[8][4];
        #pragma unroll
        for (int nt=0;nt<8;nt++){ Sv[nt][0]=0.f;Sv[nt][1]=0.f;Sv[nt][2]=0.f;Sv[nt][3]=0.f; }
        #pragma unroll
        for (int ks=0;ks<4;ks++){
            #pragma unroll
            for (int pr=0;pr<4;pr++){
                uint32_t kh4[4], kl4[4];
                const uint32_t ka = sb + swz128(krow0 + pr*16, ks*2 + (g&1));
                LDSM4(kh4, ka);
                LDSM4(kl4, ka + APL);
                #pragma unroll
                for (int s2=0;s2<2;s2++){
                    const int nt = pr*2+s2;
                    uint32_t* bh = &kh4[s2*2];
                    uint32_t* bl = &kl4[s2*2];
                    MMA16816(Sv[nt], qh[ks], bh);
                    MMA16816(Sv[nt], qh[ks], bl);
                    MMA16816(Sv[nt], ql[ks], bh);
                }
            }
        }

        // ---- softmax numerator (no running max; offset cancels in 1/l) ----
        #pragma unroll
        for (int hh=0;hh<2;hh++){
            const int i0 = hh*2;
            float sum = 0.f;
            #pragma unroll
            for (int nt=0;nt<8;nt++){
                Sv[nt][i0]   = ex2f(Sv[nt][i0]  *SC); sum += Sv[nt][i0];
                Sv[nt][i0+1] = ex2f(Sv[nt][i0+1]*SC); sum += Sv[nt][i0+1];
            }
            sum += __shfl_xor_sync(0xffffffffu, sum, 1);
            sum += __shfl_xor_sync(0xffffffffu, sum, 2);
            lrun[hh] += sum;
        }

        // ---- O += P @ V ----
        #pragma unroll
        for (int kt=0;kt<4;kt++){
            uint32_t ph[4], pl[4];
            split2(Sv[2*kt][0],   Sv[2*kt][1],   ph[0], pl[0]);
            split2(Sv[2*kt][2],   Sv[2*kt][3],   ph[1], pl[1]);
            split2(Sv[2*kt+1][0], Sv[2*kt+1][1], ph[2], pl[2]);
            split2(Sv[2*kt+1][2], Sv[2*kt+1][3], ph[3], pl[3]);
            #pragma unroll
            for (int pr=0;pr<4;pr++){
                uint32_t vh4[4], vl4[4];
                const uint32_t va = sb + 2*APL + swz128(kt*16 + vrow0, pr*2 + (l>>4));
                LDSM4T(vh4, va);
                LDSM4T(vl4, va + APL);
                #pragma unroll
                for (int s2=0;s2<2;s2++){
                    const int nt = pr*2+s2;
                    uint32_t* vh = &vh4[s2*2];
                    uint32_t* vl = &vl4[s2*2];
                    MMA16816(O[nt], ph, vh);
                    MMA16816(O[nt], ph, vl);
                    MMA16816(O[nt], pl, vh);
                }
            }
        }
    }

    // ---- normalize + write hi/lo planes [B,S,D] ----
    const int b = bhid>>4, hhead = bhid&15;
    #pragma unroll
    for (int hh=0;hh<2;hh++){
        const float inv = 1.f / lrun[hh];
        const int row = qt*128 + wm + (l>>2) + hh*8;
        const size_t obase = ((size_t)b*S_ + row)*D_ + hhead*HD_;
        #pragma unroll
        for (int nt=0;nt<8;nt++){
            uint32_t h, lo;
            split2(O[nt][hh*2+0]*inv, O[nt][hh*2+1]*inv, h, lo);
            const size_t o = obase + nt*8 + (l&3)*2;
            *reinterpret_cast<uint32_t*>(&g_ah[o]) = h;
            *reinterpret_cast<uint32_t*>(&g_al[o]) = lo;
        }
    }
    #undef A_ISSUE
}

// ---------------- launch ----------------
extern "C" void kernel_launch(void* const* d_in, const int* in_sizes, int n_in,
                              void* d_out, int out_size)
{
    const float* X  = (const float*)d_in[0];
    const float* Wq = (const float*)d_in[1];
    const float* bq = (const float*)d_in[2];
    const float* Wk = (const float*)d_in[3];
    const float* bk = (const float*)d_in[4];
    const float* Wv = (const float*)d_in[5];
    const float* bv = (const float*)d_in[6];
    const float* Wo = (const float*)d_in[7];
    const float* bo = (const float*)d_in[8];
    float* out = (float*)d_out;

    cudaFuncSetAttribute(qkv_k,  cudaFuncAttributeMaxDynamicSharedMemorySize, GSMEM);
    cudaFuncSetAttribute(out_k,  cudaFuncAttributeMaxDynamicSharedMemorySize, GSMEM);
    cudaFuncSetAttribute(attn_k, cudaFuncAttributeMaxDynamicSharedMemorySize, ASMEM);

    split_x<<<M_*D_/(256*8), 256>>>(X);
    transpose_w<<<dim3(32,32,4), 256>>>(Wq, Wk, Wv, Wo);
    qkv_k<<<dim3(D_/128, M_/128, 3), 256, GSMEM>>>(bq, bk, bv);
    attn_k<<<dim3(S_/128, B_*H_), 256, ASMEM>>>();
    out_k<<<dim3(D_/128, M_/128), 256, GSMEM>>>(bo, out);
}

// round 14
// speedup vs baseline: 1.0872x; 1.0139x over previous
#include <cuda_runtime.h>
#include <cuda_bf16.h>
#include <cstdint>

#define D_  1024
#define H_  16
#define HD_ 64
#define B_  2
#define S_  2048
#define M_  (B_*S_)   // 4096

typedef __nv_bfloat16 bf;

// ---------------- scratch planes (bf16 hi/lo) ----------------
__device__ bf g_xh[M_*D_], g_xl[M_*D_];       // split X [B*S, D]
__device__ bf g_wh[4*D_*D_], g_wl[4*D_*D_];   // transposed W [N,K] x4
__device__ bf g_qh[M_*D_], g_ql[M_*D_];       // [B,H,S,HD]
__device__ bf g_kh[M_*D_], g_kl[M_*D_];
__device__ bf g_vh[M_*D_], g_vl[M_*D_];
__device__ bf g_ah[M_*D_], g_al[M_*D_];       // attn out [B,S,D]

// ================= helpers =================
__device__ __forceinline__ uint32_t smem_u32(const void* p){
    uint32_t a;
    asm("{ .reg .u64 t; cvta.to.shared.u64 t, %1; cvt.u32.u64 %0, t; }":"=r"(a):"l"(p));
    return a;
}
__device__ __forceinline__ float ex2f(float x){
    float y; asm("ex2.approx.ftz.f32 %0, %1;":"=f"(y):"f"(x)); return y;
}
__device__ __forceinline__ uint32_t bfpack(float x, float y){
    __nv_bfloat162 t = __floats2bfloat162_rn(x, y);
    return *reinterpret_cast<uint32_t*>(&t);
}
__device__ __forceinline__ void split2(float x, float y, uint32_t& hi, uint32_t& lo){
    __nv_bfloat16 hx = __float2bfloat16_rn(x), hy = __float2bfloat16_rn(y);
    __nv_bfloat162 hh; hh.x = hx; hh.y = hy;
    hi = *reinterpret_cast<uint32_t*>(&hh);
    lo = bfpack(x - __bfloat162float(hx), y - __bfloat162float(hy));
}

#define LDSM4(R,A)  asm volatile("ldmatrix.sync.aligned.m8n8.x4.shared.b16 {%0,%1,%2,%3}, [%4];" \
    :"=r"((R)[0]),"=r"((R)[1]),"=r"((R)[2]),"=r"((R)[3]):"r"(A))
#define LDSM4T(R,A) asm volatile("ldmatrix.sync.aligned.m8n8.x4.trans.shared.b16 {%0,%1,%2,%3}, [%4];" \
    :"=r"((R)[0]),"=r"((R)[1]),"=r"((R)[2]),"=r"((R)[3]):"r"(A))
#define MMA16816(C,A,Bv) asm volatile( \
    "mma.sync.aligned.m16n8k16.row.col.f32.bf16.bf16.f32 {%0,%1,%2,%3},{%4,%5,%6,%7},{%8,%9},{%0,%1,%2,%3};" \
    :"+f"((C)[0]),"+f"((C)[1]),"+f"((C)[2]),"+f"((C)[3]) \
    :"r"((A)[0]),"r"((A)[1]),"r"((A)[2]),"r"((A)[3]),"r"((Bv)[0]),"r"((Bv)[1]))

#define CP16(dst,src) asm volatile("cp.async.cg.shared.global [%0], [%1], 16;"::"r"(dst),"l"(src):"memory")
#define CP_COMMIT()   asm volatile("cp.async.commit_group;":::"memory")
#define CP_WAIT1()    asm volatile("cp.async.wait_group 1;":::"memory")
#define CP_WAIT0()    asm volatile("cp.async.wait_group 0;":::"memory")

// conflict-free XOR swizzles (byte offsets)
__device__ __forceinline__ uint32_t swz64 (int row, int c){ return (uint32_t)(row*64  + ((c ^ ((row>>1)&3))<<4)); }
__device__ __forceinline__ uint32_t swz128(int row, int c){ return (uint32_t)(row*128 + ((c ^ (row&7))<<4)); }

// ================= prep: split X into bf16 hi/lo planes =================
__global__ void __launch_bounds__(256)
split_x(const float* __restrict__ X)
{
    const int i0 = (blockIdx.x*256 + threadIdx.x)*8;
    float4 a = *reinterpret_cast<const float4*>(X + i0);
    float4 b = *reinterpret_cast<const float4*>(X + i0 + 4);
    uint4 h, lo;
    split2(a.x,a.y,h.x,lo.x); split2(a.z,a.w,h.y,lo.y);
    split2(b.x,b.y,h.z,lo.z); split2(b.z,b.w,h.w,lo.w);
    *reinterpret_cast<uint4*>(&g_xh[i0]) = h;
    *reinterpret_cast<uint4*>(&g_xl[i0]) = lo;
}

// ================= prep: transpose W -> bf16 hi/lo [N,K] =================
__global__ void __launch_bounds__(256)
transpose_w(const float* __restrict__ Wq, const float* __restrict__ Wk,
            const float* __restrict__ Wv, const float* __restrict__ Wo)
{
    __shared__ float t[32][33];
    const int z = blockIdx.z;
    const float* W = (z==0)?Wq:(z==1)?Wk:(z==2)?Wv:Wo;
    bf* Oh = g_wh + (size_t)z*D_*D_;
    bf* Ol = g_wl + (size_t)z*D_*D_;
    const int bx = blockIdx.x*32, by = blockIdx.y*32;
    const int tx = threadIdx.x&31, ty = threadIdx.x>>5;
    #pragma unroll
    for (int r=0;r<32;r+=8) t[ty+r][tx] = W[(size_t)(by+ty+r)*D_ + bx+tx];
    __syncthreads();
    #pragma unroll
    for (int r=0;r<32;r+=8){
        const float v = t[tx][ty+r];
        const bf h = __float2bfloat16_rn(v);
        const size_t o = (size_t)(bx+ty+r)*D_ + by+tx;
        Oh[o] = h;
        Ol[o] = __float2bfloat16_rn(v - __bfloat162float(h));
    }
}

// ================= bf16x3 GEMM: 128x128 tile, k-chunk 32, 3-stage (R10 config) =================
// stage: Ah(8K) Al(8K) Bh(8K) Bl(8K) = 32KB, 64B rows swz64
#define GPLANE 8192
#define GSTG   32768
#define GSMEM  (3*GSTG)   // 98304

template<int MODE>  // 0: head-layout bf16 hi/lo out; 1: flat fp32 out
__device__ __forceinline__ void gemm_body(const bf* __restrict__ Ah, const bf* __restrict__ Al,
                                          const bf* __restrict__ Bh, const bf* __restrict__ Bl,
                                          const float* __restrict__ bias,
                                          float* __restrict__ outf,
                                          bf* __restrict__ oh, bf* __restrict__ ol)
{
    extern __shared__ __align__(128) char sm[];
    const uint32_t su = smem_u32(sm);
    const int tid = threadIdx.x, l = tid&31, w = tid>>5;
    const int wm = (w&3)*32, wn = (w>>2)*64;
    const int m0 = blockIdx.y*128, n0 = blockIdx.x*128;

    const int p = tid>>6, sub = tid&63;
    const bf* srcb = (p==0)?Ah:(p==1)?Al:(p==2)?Bh:Bl;
    const int rbase = (p<2)?m0:n0;

    #define G_ISSUE(ch) do{ \
        const uint32_t _st = su + (uint32_t)((ch)%3)*GSTG + p*GPLANE; \
        const bf* _sp = srcb + (size_t)rbase*D_ + (ch)*32; \
        _Pragma("unroll") for (int i=0;i<8;i++){ \
            const int _idx = sub + 64*i, _r = _idx>>2, _c = _idx&3; \
            CP16(_st + swz64(_r,_c), _sp + (size_t)_r*D_ + _c*8); } \
        CP_COMMIT(); }while(0)

    float C[2][8][4];
    #pragma unroll
    for (int mt=0;mt<2;mt++)
        #pragma unroll
        for (int nt=0;nt<8;nt++){ C[mt][nt][0]=0.f;C[mt][nt][1]=0.f;C[mt][nt][2]=0.f;C[mt][nt][3]=0.f; }

    G_ISSUE(0); G_ISSUE(1);

    const int g = l>>3;
    const int arow0 = wm + (l&15);
    const int brow0 = wn + ((g>>1)&1)*8 + (l&7);

    for (int c=0;c<32;c++){
        if (c<30) CP_WAIT1(); else CP_WAIT0();
        __syncthreads();
        if (c+2<32) G_ISSUE(c+2);
        const uint32_t sb = su + (uint32_t)(c%3)*GSTG;
        #pragma unroll
        for (int ks=0;ks<2;ks++){
            uint32_t ah[2][4], al2[2][4];
            #pragma unroll
            for (int mt=0;mt<2;mt++){
                const int row = arow0 + mt*16, cc = ks*2 + (l>>4);
                const uint32_t a = sb + swz64(row,cc);
                LDSM4(ah[mt], a);
                LDSM4(al2[mt], a + GPLANE);
            }
            #pragma unroll
            for (int pr=0;pr<4;pr++){
                uint32_t bh4[4], bl4[4];
                const int row = brow0 + pr*16, cc = ks*2 + (g&1);
                const uint32_t b = sb + 2*GPLANE + swz64(row,cc);
                LDSM4(bh4, b);
                LDSM4(bl4, b + GPLANE);
                #pragma unroll
                for (int s2=0;s2<2;s2++){
                    const int nt = pr*2+s2;
                    uint32_t* bh = &bh4[s2*2];
                    uint32_t* bl = &bl4[s2*2];
                    #pragma unroll
                    for (int mt=0;mt<2;mt++){
                        MMA16816(C[mt][nt], ah[mt],  bh);
                        MMA16816(C[mt][nt], ah[mt],  bl);
                        MMA16816(C[mt][nt], al2[mt], bh);
                    }
                }
            }
        }
    }

    #pragma unroll
    for (int mt=0;mt<2;mt++){
        #pragma unroll
        for (int nt=0;nt<8;nt++){
            const int col = n0 + wn + nt*8 + (l&3)*2;
            const float bx = bias[col], by = bias[col+1];
            #pragma unroll
            for (int hh=0;hh<2;hh++){
                const int row = m0 + wm + mt*16 + (l>>2) + hh*8;
                const float vx = C[mt][nt][hh*2+0] + bx;
                const float vy = C[mt][nt][hh*2+1] + by;
                if (MODE==0){
                    uint32_t h, lo; split2(vx, vy, h, lo);
                    const int b = row>>11, sq = row&(S_-1);
                    const int hd_h = col>>6, hd = col&(HD_-1);
                    const size_t o = (((size_t)b*H_+hd_h)*S_+sq)*HD_+hd;
                    *reinterpret_cast<uint32_t*>(&oh[o]) = h;
                    *reinterpret_cast<uint32_t*>(&ol[o]) = lo;
                } else {
                    float2 v; v.x = vx; v.y = vy;
                    *reinterpret_cast<float2*>(&outf[(size_t)row*D_ + col]) = v;
                }
            }
        }
    }
    #undef G_ISSUE
}

__global__ void __launch_bounds__(256,2)
qkv_k(const float* __restrict__ bq, const float* __restrict__ bk, const float* __restrict__ bv)
{
    const int z = blockIdx.z;
    const float* bias = (z==0)?bq:(z==1)?bk:bv;
    bf* oh = (z==0)?g_qh:(z==1)?g_kh:g_vh;
    bf* ol = (z==0)?g_ql:(z==1)?g_kl:g_vl;
    gemm_body<0>(g_xh, g_xl, g_wh + (size_t)z*D_*D_, g_wl + (size_t)z*D_*D_,
                 bias, nullptr, oh, ol);
}

__global__ void __launch_bounds__(256,2)
out_k(const float* __restrict__ bo, float* __restrict__ out)
{
    gemm_body<1>(g_ah, g_al, g_wh + (size_t)3*D_*D_, g_wl + (size_t)3*D_*D_,
                 bo, out, nullptr, nullptr);
}

// ================= flash attention: 3-stage KV ring, Q staged through stage2 =================
// smem: 3 KV stages of 32KB (Kh 8K | Kl 8K | Vh 8K | Vl 8K) = 96KB; Q borrows stage2 at startup.
#define APL  8192
#define ASTG 32768
#define ASMEM (3*ASTG)   // 98304 -> 2 CTAs/SM

__global__ void __launch_bounds__(256,2)
attn_k()
{
    extern __shared__ __align__(128) char sm[];
    const uint32_t su = smem_u32(sm);
    const int tid = threadIdx.x, l = tid&31, w = tid>>5;
    const int bhid = blockIdx.y, qt = blockIdx.x;
    const int wm = w*16;
    const size_t bh_off = (size_t)bhid*S_*HD_;

    const int p = tid>>6, sub = tid&63;
    const bf* kvsrc = ((p==0)?g_kh:(p==1)?g_kl:(p==2)?g_vh:g_vl) + bh_off;
    #define A_ISSUE(it) do{ \
        const uint32_t _st = su + (uint32_t)((it)%3)*ASTG + p*APL; \
        const bf* _sp = kvsrc + (size_t)(it)*64*HD_; \
        _Pragma("unroll") for (int i=0;i<8;i++){ \
            const int _idx = sub + 64*i, _r = _idx>>3, _c = _idx&7; \
            CP16(_st + swz128(_r,_c), _sp + (size_t)_r*HD_ + _c*8); } \
        CP_COMMIT(); }while(0)

    // ---- prologue: Q -> stage2 (borrowed), then fragments -> registers ----
    {
        const int p2 = tid>>7, sub2 = tid&127;
        const bf* qs = ((p2==0)?g_qh:g_ql) + bh_off + (size_t)qt*128*HD_;
        const uint32_t qdst = su + 2*ASTG + p2*16384;
        #pragma unroll
        for (int i=0;i<8;i++){
            const int idx = sub2 + 128*i, r = idx>>3, c = idx&7;
            CP16(qdst + swz128(r,c), qs + (size_t)r*HD_ + c*8);
        }
    }
    CP_COMMIT();        // group: Q
    A_ISSUE(0);         // group: kv0 -> stage0

    uint32_t qh[4][4], ql[4][4];
    const int g = l>>3;
    const int qrow = wm + (l&15);
    const int krow0 = ((g>>1)&1)*8 + (l&7);
    const int vrow0 = (l&15);

    CP_WAIT1();         // Q complete (kv0 may pend)
    __syncthreads();
    #pragma unroll
    for (int ks=0;ks<4;ks++){
        const uint32_t a = su + 2*ASTG + swz128(qrow, ks*2 + (l>>4));
        LDSM4(qh[ks], a);
        LDSM4(ql[ks], a + 16384);
    }
    __syncthreads();    // all warps done reading Q before stage2 is recycled
    A_ISSUE(1);         // kv1 -> stage1

    float O[8][4];
    #pragma unroll
    for (int nt=0;nt<8;nt++){ O[nt][0]=0.f;O[nt][1]=0.f;O[nt][2]=0.f;O[nt][3]=0.f; }
    float lrun[2] = {0.f,0.f};
    const float SC = 0.18033688011f;   // 0.125 * log2(e); constant offset cancels in 1/l

    const int NIT = S_/64;
    for (int it=0; it<NIT; ++it){
        if (it < NIT-1) CP_WAIT1(); else CP_WAIT0();   // stage it%3 ready
        __syncthreads();                               // all warps past reads of stage (it+2)%3
        if (it+2 < NIT) A_ISSUE(it+2);
        const uint32_t sb = su + (uint32_t)(it%3)*ASTG;

        // ---- S = Q @ K^T ----
        float Sv[8][4];
        #pragma unroll
        for (int nt=0;nt<8;nt++){ Sv[nt][0]=0.f;Sv[nt][1]=0.f;Sv[nt][2]=0.f;Sv[nt][3]=0.f; }
        #pragma unroll
        for (int ks=0;ks<4;ks++){
            #pragma unroll
            for (int pr=0;pr<4;pr++){
                uint32_t kh4[4], kl4[4];
                const uint32_t ka = sb + swz128(krow0 + pr*16, ks*2 + (g&1));
                LDSM4(kh4, ka);
                LDSM4(kl4, ka + APL);
                #pragma unroll
                for (int s2=0;s2<2;s2++){
                    const int nt = pr*2+s2;
                    uint32_t* bh = &kh4[s2*2];
                    uint32_t* bl = &kl4[s2*2];
                    MMA16816(Sv[nt], qh[ks], bh);
                    MMA16816(Sv[nt], qh[ks], bl);
                    MMA16816(Sv[nt], ql[ks], bh);
                }
            }
        }

        // ---- softmax numerator (no running max; offset cancels in 1/l) ----
        #pragma unroll
        for (int hh=0;hh<2;hh++){
            const int i0 = hh*2;
            float sum = 0.f;
            #pragma unroll
            for (int nt=0;nt<8;nt++){
                Sv[nt][i0]   = ex2f(Sv[nt][i0]  *SC); sum += Sv[nt][i0];
                Sv[nt][i0+1] = ex2f(Sv[nt][i0+1]*SC); sum += Sv[nt][i0+1];
            }
            sum += __shfl_xor_sync(0xffffffffu, sum, 1);
            sum += __shfl_xor_sync(0xffffffffu, sum, 2);
            lrun[hh] += sum;
        }

        // ---- O += P @ V ----
        #pragma unroll
        for (int kt=0;kt<4;kt++){
            uint32_t ph[4], pl[4];
            split2(Sv[2*kt][0],   Sv[2*kt][1],   ph[0], pl[0]);
            split2(Sv[2*kt][2],   Sv[2*kt][3],   ph[1], pl[1]);
            split2(Sv[2*kt+1][0], Sv[2*kt+1][1], ph[2], pl[2]);
            split2(Sv[2*kt+1][2], Sv[2*kt+1][3], ph[3], pl[3]);
            #pragma unroll
            for (int pr=0;pr<4;pr++){
                uint32_t vh4[4], vl4[4];
                const uint32_t va = sb + 2*APL + swz128(kt*16 + vrow0, pr*2 + (l>>4));
                LDSM4T(vh4, va);
                LDSM4T(vl4, va + APL);
                #pragma unroll
                for (int s2=0;s2<2;s2++){
                    const int nt = pr*2+s2;
                    uint32_t* vh = &vh4[s2*2];
                    uint32_t* vl = &vl4[s2*2];
                    MMA16816(O[nt], ph, vh);
                    MMA16816(O[nt], ph, vl);
                    MMA16816(O[nt], pl, vh);
                }
            }
        }
    }

    // ---- normalize + write hi/lo planes [B,S,D] ----
    const int b = bhid>>4, hhead = bhid&15;
    #pragma unroll
    for (int hh=0;hh<2;hh++){
        const float inv = 1.f / lrun[hh];
        const int row = qt*128 + wm + (l>>2) + hh*8;
        const size_t obase = ((size_t)b*S_ + row)*D_ + hhead*HD_;
        #pragma unroll
        for (int nt=0;nt<8;nt++){
            uint32_t h, lo;
            split2(O[nt][hh*2+0]*inv, O[nt][hh*2+1]*inv, h, lo);
            const size_t o = obase + nt*8 + (l&3)*2;
            *reinterpret_cast<uint32_t*>(&g_ah[o]) = h;
            *reinterpret_cast<uint32_t*>(&g_al[o]) = lo;
        }
    }
    #undef A_ISSUE
}

// ---------------- launch ----------------
extern "C" void kernel_launch(void* const* d_in, const int* in_sizes, int n_in,
                              void* d_out, int out_size)
{
    const float* X  = (const float*)d_in[0];
    const float* Wq = (const float*)d_in[1];
    const float* bq = (const float*)d_in[2];
    const float* Wk = (const float*)d_in[3];
    const float* bk = (const float*)d_in[4];
    const float* Wv = (const float*)d_in[5];
    const float* bv = (const float*)d_in[6];
    const float* Wo = (const float*)d_in[7];
    const float* bo = (const float*)d_in[8];
    float* out = (float*)d_out;

    cudaFuncSetAttribute(qkv_k,  cudaFuncAttributeMaxDynamicSharedMemorySize, GSMEM);
    cudaFuncSetAttribute(out_k,  cudaFuncAttributeMaxDynamicSharedMemorySize, GSMEM);
    cudaFuncSetAttribute(attn_k, cudaFuncAttributeMaxDynamicSharedMemorySize, ASMEM);

    split_x<<<M_*D_/(256*8), 256>>>(X);
    transpose_w<<<dim3(32,32,4), 256>>>(Wq, Wk, Wv, Wo);
    qkv_k<<<dim3(D_/128, M_/128, 3), 256, GSMEM>>>(bq, bk, bv);
    attn_k<<<dim3(S_/128, B_*H_), 256, ASMEM>>>();
    out_k<<<dim3(D_/128, M_/128), 256, GSMEM>>>(bo, out);
}

// round 16
// speedup vs baseline: 1.2736x; 1.1715x over previous
#include <cuda_runtime.h>
#include <cuda_bf16.h>
#include <cuda_fp16.h>
#include <cstdint>

#define D_  1024
#define H_  16
#define HD_ 64
#define B_  2
#define S_  2048
#define M_  (B_*S_)   // 4096

typedef __nv_bfloat16 bf;
typedef __half hf;

// ---------------- scratch planes ----------------
__device__ bf g_xh[M_*D_], g_xl[M_*D_];       // split X [B*S, D] (bf16 hi/lo)
__device__ bf g_wh[4*D_*D_], g_wl[4*D_*D_];   // transposed W [N,K] x4 (bf16 hi/lo)
__device__ hf gq_h[M_*D_];                    // Q [B,H,S,HD] fp16 (single plane)
__device__ hf gk_h[M_*D_], gk_l[M_*D_];       // K fp16 hi/lo
__device__ hf gv_h[M_*D_], gv_l[M_*D_];       // V fp16 hi/lo
__device__ bf g_ah[M_*D_], g_al[M_*D_];       // attn out [B,S,D] (bf16 hi/lo)

// ================= helpers =================
__device__ __forceinline__ uint32_t smem_u32(const void* p){
    uint32_t a;
    asm("{ .reg .u64 t; cvta.to.shared.u64 t, %1; cvt.u32.u64 %0, t; }":"=r"(a):"l"(p));
    return a;
}
__device__ __forceinline__ float ex2f(float x){
    float y; asm("ex2.approx.ftz.f32 %0, %1;":"=f"(y):"f"(x)); return y;
}
__device__ __forceinline__ uint32_t bfpack(float x, float y){
    __nv_bfloat162 t = __floats2bfloat162_rn(x, y);
    return *reinterpret_cast<uint32_t*>(&t);
}
__device__ __forceinline__ void split2(float x, float y, uint32_t& hi, uint32_t& lo){
    __nv_bfloat16 hx = __float2bfloat16_rn(x), hy = __float2bfloat16_rn(y);
    __nv_bfloat162 hh; hh.x = hx; hh.y = hy;
    hi = *reinterpret_cast<uint32_t*>(&hh);
    lo = bfpack(x - __bfloat162float(hx), y - __bfloat162float(hy));
}
// fp16 split
__device__ __forceinline__ void split2h(float x, float y, uint32_t& hi, uint32_t& lo){
    __half hx = __float2half_rn(x), hy = __float2half_rn(y);
    __half2 hh = __halves2half2(hx, hy);
    hi = *reinterpret_cast<uint32_t*>(&hh);
    __half2 ll = __floats2half2_rn(x - __half2float(hx), y - __half2float(hy));
    lo = *reinterpret_cast<uint32_t*>(&ll);
}
__device__ __forceinline__ uint32_t h2pack(float x, float y){
    __half2 t = __floats2half2_rn(x, y);
    return *reinterpret_cast<uint32_t*>(&t);
}

#define LDSM4(R,A)  asm volatile("ldmatrix.sync.aligned.m8n8.x4.shared.b16 {%0,%1,%2,%3}, [%4];" \
    :"=r"((R)[0]),"=r"((R)[1]),"=r"((R)[2]),"=r"((R)[3]):"r"(A))
#define LDSM4T(R,A) asm volatile("ldmatrix.sync.aligned.m8n8.x4.trans.shared.b16 {%0,%1,%2,%3}, [%4];" \
    :"=r"((R)[0]),"=r"((R)[1]),"=r"((R)[2]),"=r"((R)[3]):"r"(A))
#define MMA16816(C,A,Bv) asm volatile( \
    "mma.sync.aligned.m16n8k16.row.col.f32.bf16.bf16.f32 {%0,%1,%2,%3},{%4,%5,%6,%7},{%8,%9},{%0,%1,%2,%3};" \
    :"+f"((C)[0]),"+f"((C)[1]),"+f"((C)[2]),"+f"((C)[3]) \
    :"r"((A)[0]),"r"((A)[1]),"r"((A)[2]),"r"((A)[3]),"r"((Bv)[0]),"r"((Bv)[1]))
#define MMAH(C,A,Bv) asm volatile( \
    "mma.sync.aligned.m16n8k16.row.col.f32.f16.f16.f32 {%0,%1,%2,%3},{%4,%5,%6,%7},{%8,%9},{%0,%1,%2,%3};" \
    :"+f"((C)[0]),"+f"((C)[1]),"+f"((C)[2]),"+f"((C)[3]) \
    :"r"((A)[0]),"r"((A)[1]),"r"((A)[2]),"r"((A)[3]),"r"((Bv)[0]),"r"((Bv)[1]))

#define CP16(dst,src) asm volatile("cp.async.cg.shared.global [%0], [%1], 16;"::"r"(dst),"l"(src):"memory")
#define CP_COMMIT()   asm volatile("cp.async.commit_group;":::"memory")
#define CP_WAIT1()    asm volatile("cp.async.wait_group 1;":::"memory")
#define CP_WAIT0()    asm volatile("cp.async.wait_group 0;":::"memory")

// conflict-free XOR swizzles (byte offsets)
__device__ __forceinline__ uint32_t swz64 (int row, int c){ return (uint32_t)(row*64  + ((c ^ ((row>>1)&3))<<4)); }
__device__ __forceinline__ uint32_t swz128(int row, int c){ return (uint32_t)(row*128 + ((c ^ (row&7))<<4)); }

// ================= prep: split X into bf16 hi/lo planes =================
__global__ void __launch_bounds__(256)
split_x(const float* __restrict__ X)
{
    const int i0 = (blockIdx.x*256 + threadIdx.x)*8;
    float4 a = *reinterpret_cast<const float4*>(X + i0);
    float4 b = *reinterpret_cast<const float4*>(X + i0 + 4);
    uint4 h, lo;
    split2(a.x,a.y,h.x,lo.x); split2(a.z,a.w,h.y,lo.y);
    split2(b.x,b.y,h.z,lo.z); split2(b.z,b.w,h.w,lo.w);
    *reinterpret_cast<uint4*>(&g_xh[i0]) = h;
    *reinterpret_cast<uint4*>(&g_xl[i0]) = lo;
}

// ================= prep: transpose W -> bf16 hi/lo [N,K] =================
__global__ void __launch_bounds__(256)
transpose_w(const float* __restrict__ Wq, const float* __restrict__ Wk,
            const float* __restrict__ Wv, const float* __restrict__ Wo)
{
    __shared__ float t[32][33];
    const int z = blockIdx.z;
    const float* W = (z==0)?Wq:(z==1)?Wk:(z==2)?Wv:Wo;
    bf* Oh = g_wh + (size_t)z*D_*D_;
    bf* Ol = g_wl + (size_t)z*D_*D_;
    const int bx = blockIdx.x*32, by = blockIdx.y*32;
    const int tx = threadIdx.x&31, ty = threadIdx.x>>5;
    #pragma unroll
    for (int r=0;r<32;r+=8) t[ty+r][tx] = W[(size_t)(by+ty+r)*D_ + bx+tx];
    __syncthreads();
    #pragma unroll
    for (int r=0;r<32;r+=8){
        const float v = t[tx][ty+r];
        const bf h = __float2bfloat16_rn(v);
        const size_t o = (size_t)(bx+ty+r)*D_ + by+tx;
        Oh[o] = h;
        Ol[o] = __float2bfloat16_rn(v - __bfloat162float(h));
    }
}

// ================= bf16x3 GEMM: 128x128 tile, k-chunk 32, 3-stage =================
// stage: Ah(8K) Al(8K) Bh(8K) Bl(8K) = 32KB, 64B rows swz64
#define GPLANE 8192
#define GSTG   32768
#define GSMEM  (3*GSTG)   // 98304

template<int MODE>  // 0: head-layout fp16 out (oh always, ol optional); 1: flat fp32 out
__device__ __forceinline__ void gemm_body(const bf* __restrict__ Ah, const bf* __restrict__ Al,
                                          const bf* __restrict__ Bh, const bf* __restrict__ Bl,
                                          const float* __restrict__ bias,
                                          float* __restrict__ outf,
                                          hf* __restrict__ oh, hf* __restrict__ ol)
{
    extern __shared__ __align__(128) char sm[];
    const uint32_t su = smem_u32(sm);
    const int tid = threadIdx.x, l = tid&31, w = tid>>5;
    const int wm = (w&3)*32, wn = (w>>2)*64;
    const int m0 = blockIdx.y*128, n0 = blockIdx.x*128;

    const int p = tid>>6, sub = tid&63;
    const bf* srcb = (p==0)?Ah:(p==1)?Al:(p==2)?Bh:Bl;
    const int rbase = (p<2)?m0:n0;

    #define G_ISSUE(ch) do{ \
        const uint32_t _st = su + (uint32_t)((ch)%3)*GSTG + p*GPLANE; \
        const bf* _sp = srcb + (size_t)rbase*D_ + (ch)*32; \
        _Pragma("unroll") for (int i=0;i<8;i++){ \
            const int _idx = sub + 64*i, _r = _idx>>2, _c = _idx&3; \
            CP16(_st + swz64(_r,_c), _sp + (size_t)_r*D_ + _c*8); } \
        CP_COMMIT(); }while(0)

    float C[2][8][4];
    #pragma unroll
    for (int mt=0;mt<2;mt++)
        #pragma unroll
        for (int nt=0;nt<8;nt++){ C[mt][nt][0]=0.f;C[mt][nt][1]=0.f;C[mt][nt][2]=0.f;C[mt][nt][3]=0.f; }

    G_ISSUE(0); G_ISSUE(1);

    const int g = l>>3;
    const int arow0 = wm + (l&15);
    const int brow0 = wn + ((g>>1)&1)*8 + (l&7);

    for (int c=0;c<32;c++){
        if (c<30) CP_WAIT1(); else CP_WAIT0();
        __syncthreads();
        if (c+2<32) G_ISSUE(c+2);
        const uint32_t sb = su + (uint32_t)(c%3)*GSTG;
        #pragma unroll
        for (int ks=0;ks<2;ks++){
            uint32_t ah[2][4], al2[2][4];
            #pragma unroll
            for (int mt=0;mt<2;mt++){
                const int row = arow0 + mt*16, cc = ks*2 + (l>>4);
                const uint32_t a = sb + swz64(row,cc);
                LDSM4(ah[mt], a);
                LDSM4(al2[mt], a + GPLANE);
            }
            #pragma unroll
            for (int pr=0;pr<4;pr++){
                uint32_t bh4[4], bl4[4];
                const int row = brow0 + pr*16, cc = ks*2 + (g&1);
                const uint32_t b = sb + 2*GPLANE + swz64(row,cc);
                LDSM4(bh4, b);
                LDSM4(bl4, b + GPLANE);
                #pragma unroll
                for (int s2=0;s2<2;s2++){
                    const int nt = pr*2+s2;
                    uint32_t* bh = &bh4[s2*2];
                    uint32_t* bl = &bl4[s2*2];
                    #pragma unroll
                    for (int mt=0;mt<2;mt++){
                        MMA16816(C[mt][nt], ah[mt],  bh);
                        MMA16816(C[mt][nt], ah[mt],  bl);
                        MMA16816(C[mt][nt], al2[mt], bh);
                    }
                }
            }
        }
    }

    #pragma unroll
    for (int mt=0;mt<2;mt++){
        #pragma unroll
        for (int nt=0;nt<8;nt++){
            const int col = n0 + wn + nt*8 + (l&3)*2;
            const float bx = bias[col], by = bias[col+1];
            #pragma unroll
            for (int hh=0;hh<2;hh++){
                const int row = m0 + wm + mt*16 + (l>>2) + hh*8;
                const float vx = C[mt][nt][hh*2+0] + bx;
                const float vy = C[mt][nt][hh*2+1] + by;
                if (MODE==0){
                    uint32_t h, lo; split2h(vx, vy, h, lo);
                    const int b = row>>11, sq = row&(S_-1);
                    const int hd_h = col>>6, hd = col&(HD_-1);
                    const size_t o = (((size_t)b*H_+hd_h)*S_+sq)*HD_+hd;
                    *reinterpret_cast<uint32_t*>(&oh[o]) = h;
                    if (ol) *reinterpret_cast<uint32_t*>(&ol[o]) = lo;
                } else {
                    float2 v; v.x = vx; v.y = vy;
                    *reinterpret_cast<float2*>(&outf[(size_t)row*D_ + col]) = v;
                }
            }
        }
    }
    #undef G_ISSUE
}

__global__ void __launch_bounds__(256,2)
qkv_k(const float* __restrict__ bq, const float* __restrict__ bk, const float* __restrict__ bv)
{
    const int z = blockIdx.z;
    const float* bias = (z==0)?bq:(z==1)?bk:bv;
    hf* oh = (z==0)?gq_h:(z==1)?gk_h:gv_h;
    hf* ol = (z==0)?nullptr:(z==1)?gk_l:gv_l;   // Q: single fp16 plane
    gemm_body<0>(g_xh, g_xl, g_wh + (size_t)z*D_*D_, g_wl + (size_t)z*D_*D_,
                 bias, nullptr, oh, ol);
}

__global__ void __launch_bounds__(256,2)
out_k(const float* __restrict__ bo, float* __restrict__ out)
{
    extern __shared__ char smdummy[];
    // reuse gemm_body with bf16 A planes (g_ah/g_al)
    gemm_body<1>(g_ah, g_al, g_wh + (size_t)3*D_*D_, g_wl + (size_t)3*D_*D_,
                 bo, out, nullptr, nullptr);
}

// ================= flash attention: fp16 2-term, 3-stage KV ring, Q via stage2 =================
// smem: 3 KV stages of 32KB (Kh 8K | Kl 8K | Vh 8K | Vl 8K) = 96KB; Q (16KB fp16) borrows stage2.
#define APL  8192
#define ASTG 32768
#define ASMEM (3*ASTG)   // 98304 -> 2 CTAs/SM

__global__ void __launch_bounds__(256,2)
attn_k()
{
    extern __shared__ __align__(128) char sm[];
    const uint32_t su = smem_u32(sm);
    const int tid = threadIdx.x, l = tid&31, w = tid>>5;
    const int bhid = blockIdx.y, qt = blockIdx.x;
    const int wm = w*16;
    const size_t bh_off = (size_t)bhid*S_*HD_;

    const int p = tid>>6, sub = tid&63;
    const hf* kvsrc = ((p==0)?gk_h:(p==1)?gk_l:(p==2)?gv_h:gv_l) + bh_off;
    #define A_ISSUE(it) do{ \
        const uint32_t _st = su + (uint32_t)((it)%3)*ASTG + p*APL; \
        const hf* _sp = kvsrc + (size_t)(it)*64*HD_; \
        _Pragma("unroll") for (int i=0;i<8;i++){ \
            const int _idx = sub + 64*i, _r = _idx>>3, _c = _idx&7; \
            CP16(_st + swz128(_r,_c), _sp + (size_t)_r*HD_ + _c*8); } \
        CP_COMMIT(); }while(0)

    // ---- prologue: Q (single fp16 plane, 16KB) -> stage2, fragments -> registers ----
    {
        const hf* qs = gq_h + bh_off + (size_t)qt*128*HD_;
        const uint32_t qdst = su + 2*ASTG;
        #pragma unroll
        for (int i=0;i<4;i++){
            const int idx = tid + 256*i, r = idx>>3, c = idx&7;
            CP16(qdst + swz128(r,c), qs + (size_t)r*HD_ + c*8);
        }
    }
    CP_COMMIT();        // group: Q
    A_ISSUE(0);         // group: kv0 -> stage0

    uint32_t qh[4][4];
    const int g = l>>3;
    const int qrow = wm + (l&15);
    const int krow0 = ((g>>1)&1)*8 + (l&7);
    const int vrow0 = (l&15);

    CP_WAIT1();         // Q complete (kv0 may pend)
    __syncthreads();
    #pragma unroll
    for (int ks=0;ks<4;ks++)
        LDSM4(qh[ks], su + 2*ASTG + swz128(qrow, ks*2 + (l>>4)));
    __syncthreads();    // all warps done reading Q before stage2 is recycled
    A_ISSUE(1);         // kv1 -> stage1

    float O[8][4];
    #pragma unroll
    for (int nt=0;nt<8;nt++){ O[nt][0]=0.f;O[nt][1]=0.f;O[nt][2]=0.f;O[nt][3]=0.f; }
    float lrun[2] = {0.f,0.f};
    const float SC = 0.18033688011f;   // 0.125 * log2(e); constant offset cancels in 1/l

    const int NIT = S_/64;
    for (int it=0; it<NIT; ++it){
        if (it < NIT-1) CP_WAIT1(); else CP_WAIT0();   // stage it%3 ready
        __syncthreads();                               // all warps past reads of stage (it+2)%3
        if (it+2 < NIT) A_ISSUE(it+2);
        const uint32_t sb = su + (uint32_t)(it%3)*ASTG;

        // ---- S = qh @ (Kh + Kl)^T : 2-term fp16 ----
        float Sv[8][4];
        #pragma unroll
        for (int nt=0;nt<8;nt++){ Sv[nt][0]=0.f;Sv[nt][1]=0.f;Sv[nt][2]=0.f;Sv[nt][3]=0.f; }
        #pragma unroll
        for (int ks=0;ks<4;ks++){
            #pragma unroll
            for (int pr=0;pr<4;pr++){
                uint32_t kh4[4], kl4[4];
                const uint32_t ka = sb + swz128(krow0 + pr*16, ks*2 + (g&1));
                LDSM4(kh4, ka);
                LDSM4(kl4, ka + APL);
                #pragma unroll
                for (int s2=0;s2<2;s2++){
                    const int nt = pr*2+s2;
                    MMAH(Sv[nt], qh[ks], &kh4[s2*2]);
                    MMAH(Sv[nt], qh[ks], &kl4[s2*2]);
                }
            }
        }

        // ---- softmax numerator (no running max; offset cancels in 1/l) ----
        #pragma unroll
        for (int hh=0;hh<2;hh++){
            const int i0 = hh*2;
            float sum = 0.f;
            #pragma unroll
            for (int nt=0;nt<8;nt++){
                Sv[nt][i0]   = ex2f(Sv[nt][i0]  *SC); sum += Sv[nt][i0];
                Sv[nt][i0+1] = ex2f(Sv[nt][i0+1]*SC); sum += Sv[nt][i0+1];
            }
            sum += __shfl_xor_sync(0xffffffffu, sum, 1);
            sum += __shfl_xor_sync(0xffffffffu, sum, 2);
            lrun[hh] += sum;
        }

        // ---- O += ph @ (Vh + Vl) : 2-term fp16 ----
        #pragma unroll
        for (int kt=0;kt<4;kt++){
            uint32_t ph[4];
            ph[0] = h2pack(Sv[2*kt][0],   Sv[2*kt][1]);
            ph[1] = h2pack(Sv[2*kt][2],   Sv[2*kt][3]);
            ph[2] = h2pack(Sv[2*kt+1][0], Sv[2*kt+1][1]);
            ph[3] = h2pack(Sv[2*kt+1][2], Sv[2*kt+1][3]);
            #pragma unroll
            for (int pr=0;pr<4;pr++){
                uint32_t vh4[4], vl4[4];
                const uint32_t va = sb + 2*APL + swz128(kt*16 + vrow0, pr*2 + (l>>4));
                LDSM4T(vh4, va);
                LDSM4T(vl4, va + APL);
                #pragma unroll
                for (int s2=0;s2<2;s2++){
                    const int nt = pr*2+s2;
                    MMAH(O[nt], ph, &vh4[s2*2]);
                    MMAH(O[nt], ph, &vl4[s2*2]);
                }
            }
        }
    }

    // ---- normalize + write bf16 hi/lo planes [B,S,D] ----
    const int b = bhid>>4, hhead = bhid&15;
    #pragma unroll
    for (int hh=0;hh<2;hh++){
        const float inv = 1.f / lrun[hh];
        const int row = qt*128 + wm + (l>>2) + hh*8;
        const size_t obase = ((size_t)b*S_ + row)*D_ + hhead*HD_;
        #pragma unroll
        for (int nt=0;nt<8;nt++){
            uint32_t h, lo;
            split2(O[nt][hh*2+0]*inv, O[nt][hh*2+1]*inv, h, lo);
            const size_t o = obase + nt*8 + (l&3)*2;
            *reinterpret_cast<uint32_t*>(&g_ah[o]) = h;
            *reinterpret_cast<uint32_t*>(&g_al[o]) = lo;
        }
    }
    #undef A_ISSUE
}

// ---------------- launch ----------------
extern "C" void kernel_launch(void* const* d_in, const int* in_sizes, int n_in,
                              void* d_out, int out_size)
{
    const float* X  = (const float*)d_in[0];
    const float* Wq = (const float*)d_in[1];
    const float* bq = (const float*)d_in[2];
    const float* Wk = (const float*)d_in[3];
    const float* bk = (const float*)d_in[4];
    const float* Wv = (const float*)d_in[5];
    const float* bv = (const float*)d_in[6];
    const float* Wo = (const float*)d_in[7];
    const float* bo = (const float*)d_in[8];
    float* out = (float*)d_out;

    cudaFuncSetAttribute(qkv_k,  cudaFuncAttributeMaxDynamicSharedMemorySize, GSMEM);
    cudaFuncSetAttribute(out_k,  cudaFuncAttributeMaxDynamicSharedMemorySize, GSMEM);
    cudaFuncSetAttribute(attn_k, cudaFuncAttributeMaxDynamicSharedMemorySize, ASMEM);

    split_x<<<M_*D_/(256*8), 256>>>(X);
    transpose_w<<<dim3(32,32,4), 256>>>(Wq, Wk, Wv, Wo);
    qkv_k<<<dim3(D_/128, M_/128, 3), 256, GSMEM>>>(bq, bk, bv);
    attn_k<<<dim3(S_/128, B_*H_), 256, ASMEM>>>();
    out_k<<<dim3(D_/128, M_/128), 256, GSMEM>>>(bo, out);
}